// round 7
// baseline (speedup 1.0000x reference)
#include <cuda_runtime.h>
#include <cstdint>

#define BATCH 32
#define NP    576
#define NTXT  77
#define NTOK  654
#define EMB   768
#define HD    384
#define SRS   704          // padded k for AV (22*32)
#define INV_SQRT_E 0.03608439182435161f
#define DSMB  (65536 + 1024)

// ---------------- fp32 scratch ----------------
__device__ float g_t[(size_t)BATCH * NTOK * EMB];
__device__ float g_f[(size_t)BATCH * NTOK * EMB];
__device__ float g_v[(size_t)BATCH * NTOK * EMB];
__device__ float g_s[(size_t)BATCH * 2 * NTOK * SRS];
__device__ float g_m[BATCH * EMB];

// ---------------- split bf16 buffers ----------------
#define PAW ((size_t)18432 * 768)
#define HQW ((size_t)20928 * 768)
#define SXW ((size_t)64 * NTOK * SRS)
#define VTW ((size_t)BATCH * EMB * SRS)
__device__ uint16_t g_pa_h[PAW], g_pa_l[PAW];
__device__ uint16_t g_h_h[HQW],  g_h_l[HQW];
__device__ uint16_t g_q_h[HQW],  g_q_l[HQW];
__device__ uint16_t g_k_h[HQW],  g_k_l[HQW];
__device__ uint16_t g_o_h[HQW],  g_o_l[HQW];
__device__ uint16_t g_sx_h[SXW], g_sx_l[SXW];
__device__ uint16_t g_vt_h[VTW], g_vt_l[VTW];
__device__ uint16_t g_m_h[32*768], g_m_l[32*768];
__device__ uint16_t g_wh[6][768*768], g_wl[6][768*768];  // transposed [N][K]

// ---------------- helpers ----------------
__device__ __forceinline__ float warpSum(float v) {
#pragma unroll
    for (int o = 16; o; o >>= 1) v += __shfl_xor_sync(0xffffffffu, v, o);
    return v;
}
__device__ __forceinline__ float warpMax(float v) {
#pragma unroll
    for (int o = 16; o; o >>= 1) v = fmaxf(v, __shfl_xor_sync(0xffffffffu, v, o));
    return v;
}
__device__ __forceinline__ void bsplit1(float x, uint16_t& h, uint16_t& l) {
    uint32_t u = __float_as_uint(x);
    uint32_t hu = (u + 0x8000u) & 0xffff0000u;
    float lo = x - __uint_as_float(hu);
    h = (uint16_t)(hu >> 16);
    l = (uint16_t)((__float_as_uint(lo) + 0x8000u) >> 16);
}
__device__ __forceinline__ void cpa(uint32_t dst, const void* src) {
    asm volatile("cp.async.cg.shared.global [%0], [%1], 16;" :: "r"(dst), "l"(src));
}
#define CPCOMMIT asm volatile("cp.async.commit_group;")
#define CPWAIT(n) asm volatile("cp.async.wait_group %0;" :: "n"(n))

__device__ __forceinline__ void mma16(float c[4], uint32_t a0, uint32_t a1,
                                      uint32_t a2, uint32_t a3,
                                      uint32_t b0, uint32_t b1) {
    asm volatile(
        "mma.sync.aligned.m16n8k16.row.col.f32.bf16.bf16.f32 "
        "{%0,%1,%2,%3},{%4,%5,%6,%7},{%8,%9},{%0,%1,%2,%3};"
        : "+f"(c[0]), "+f"(c[1]), "+f"(c[2]), "+f"(c[3])
        : "r"(a0), "r"(a1), "r"(a2), "r"(a3), "r"(b0), "r"(b1));
}
__device__ __forceinline__ void ldsm4(uint32_t& r0, uint32_t& r1, uint32_t& r2,
                                      uint32_t& r3, uint32_t a) {
    asm volatile("ldmatrix.sync.aligned.m8n8.x4.shared.b16 {%0,%1,%2,%3}, [%4];"
                 : "=r"(r0), "=r"(r1), "=r"(r2), "=r"(r3) : "r"(a));
}

// SMEM tile layout per stage (32 KB):
//   +0     A hi  : 128 rows x 32 k bf16 as 8x8-b16 atoms, atom idx = (row>>3)*4 + (k>>3)
//   +8192  A lo
//   +16384 B hi  : 128 cols x 32 k, same layout
//   +24576 B lo
__device__ __forceinline__ void load_chunk32(
    const uint16_t* __restrict__ Ah, const uint16_t* __restrict__ Al,
    size_t lda, int armax, int row0,
    const uint16_t* __restrict__ Bh, const uint16_t* __restrict__ Bl,
    size_t ldb, int brmax, int col0,
    int kt, uint32_t sbase, int tid) {
#pragma unroll
    for (int i = 0; i < 8; i++) {
        int bufi = i >> 1;
        int r = ((i & 1) << 8) | tid;
        int row = r >> 2, kh = r & 3;
        uint32_t dst = sbase + (uint32_t)bufi * 8192u
                     + (uint32_t)(((((row >> 3) << 2) + kh) << 7) + ((row & 7) << 4));
        const uint16_t* src;
        if (bufi < 2) {
            int gr = row0 + row; if (gr > armax) gr = armax;
            src = (bufi == 0 ? Ah : Al) + (size_t)gr * lda + (size_t)(kt * 32 + kh * 8);
        } else {
            int gc = col0 + row; if (gc > brmax) gc = brmax;
            src = (bufi == 2 ? Bh : Bl) + (size_t)gc * ldb + (size_t)(kt * 32 + kh * 8);
        }
        cpa(dst, src);
    }
    CPCOMMIT;
}

// one 128x128x32 chunk (warp = 32x64), 3-term bf16
__device__ __forceinline__ void mma_chunk32(uint32_t sA, uint32_t sB,
                                            int wm, int wn, int lane,
                                            float acc[2][8][4]) {
    int l8 = lane & 7, lg = lane >> 3;
#pragma unroll
    for (int kc = 0; kc < 2; kc++) {
        uint32_t ah[2][4], al[2][4];
#pragma unroll
        for (int mi = 0; mi < 2; mi++) {
            int rg = wm * 4 + mi * 2 + (lg & 1);
            int kh = kc * 2 + (lg >> 1);
            uint32_t aa = sA + (uint32_t)((((rg << 2) + kh) << 7) + (l8 << 4));
            ldsm4(ah[mi][0], ah[mi][1], ah[mi][2], ah[mi][3], aa);
            ldsm4(al[mi][0], al[mi][1], al[mi][2], al[mi][3], aa + 8192u);
        }
#pragma unroll
        for (int nb = 0; nb < 4; nb++) {
            int cg = wn * 8 + nb * 2 + (lg >> 1);
            int kh = kc * 2 + (lg & 1);
            uint32_t ba = sB + (uint32_t)((((cg << 2) + kh) << 7) + (l8 << 4));
            uint32_t bh[4], bl[4];
            ldsm4(bh[0], bh[1], bh[2], bh[3], ba);
            ldsm4(bl[0], bl[1], bl[2], bl[3], ba + 8192u);
#pragma unroll
            for (int n2 = 0; n2 < 2; n2++) {
                int ni = nb * 2 + n2;
#pragma unroll
                for (int mi = 0; mi < 2; mi++) {
                    mma16(acc[mi][ni], ah[mi][0], ah[mi][1], ah[mi][2], ah[mi][3],
                          bh[n2 * 2], bh[n2 * 2 + 1]);
                    mma16(acc[mi][ni], ah[mi][0], ah[mi][1], ah[mi][2], ah[mi][3],
                          bl[n2 * 2], bl[n2 * 2 + 1]);
                    mma16(acc[mi][ni], al[mi][0], al[mi][1], al[mi][2], al[mi][3],
                          bh[n2 * 2], bh[n2 * 2 + 1]);
                }
            }
        }
    }
}

__device__ __forceinline__ void mm_loop(
    const uint16_t* __restrict__ Ah, const uint16_t* __restrict__ Al,
    size_t lda, int armax, int row0,
    const uint16_t* __restrict__ Bh, const uint16_t* __restrict__ Bl,
    size_t ldb, int brmax, int col0,
    int KT, uint32_t smu, int wm, int wn, int lane, float acc[2][8][4]) {
    int tid = threadIdx.x;
    load_chunk32(Ah, Al, lda, armax, row0, Bh, Bl, ldb, brmax, col0, 0, smu, tid);
    if (KT > 1)
        load_chunk32(Ah, Al, lda, armax, row0, Bh, Bl, ldb, brmax, col0, 1,
                     smu + 32768u, tid);
    for (int kt = 0; kt < KT; kt++) {
        if (kt + 1 < KT) { CPWAIT(1); } else { CPWAIT(0); }
        __syncthreads();
        uint32_t sb = smu + (uint32_t)(kt & 1) * 32768u;
        mma_chunk32(sb, sb + 16384u, wm, wn, lane, acc);
        __syncthreads();
        if (kt + 2 < KT)
            load_chunk32(Ah, Al, lda, armax, row0, Bh, Bl, ldb, brmax, col0,
                         kt + 2, sb, tid);
    }
}

#define MM_PROLOG()                                                          \
    extern __shared__ char dsm_raw[];                                        \
    char* dsm = (char*)(((uintptr_t)dsm_raw + 1023) & ~(uintptr_t)1023);     \
    uint32_t smu = (uint32_t)__cvta_generic_to_shared(dsm);                  \
    int tid = threadIdx.x, lane = tid & 31, wid = tid >> 5;                  \
    int wm = wid & 3, wn = wid >> 2;                                         \
    float acc[2][8][4] = {};                                                 \
    (void)tid;

// ---------------- generic GEMM: C = A[MxK] @ WT[NxK] + bias ------------------
__global__ void __launch_bounds__(256, 2)
gemm_lm(const uint16_t* __restrict__ Ah, const uint16_t* __restrict__ Al, int lda,
        const uint16_t* __restrict__ Bh, const uint16_t* __restrict__ Bl,
        const float* __restrict__ bias,
        float* __restrict__ Cf, uint16_t* __restrict__ Ch, uint16_t* __restrict__ Cl,
        int ldc, int M, int KT, int remap) {
    MM_PROLOG();
    int row0 = blockIdx.y * 128, col0 = blockIdx.x * 128;
    mm_loop(Ah, Al, lda, M - 1, row0, Bh, Bl, 768, 767, col0,
            KT, smu, wm, wn, lane, acc);
    int g = lane >> 2, t = lane & 3;
#pragma unroll
    for (int mi = 0; mi < 2; mi++)
#pragma unroll
        for (int e = 0; e < 2; e++) {
            int r = row0 + wm * 32 + mi * 16 + g + e * 8;
            if (r >= M) continue;
            size_t orow = remap ? ((size_t)r + (size_t)(r / NP) * 78 + 1) : (size_t)r;
#pragma unroll
            for (int ni = 0; ni < 8; ni++) {
                int c = col0 + wn * 64 + ni * 8 + t * 2;
                float v0 = acc[mi][ni][e * 2 + 0];
                float v1 = acc[mi][ni][e * 2 + 1];
                if (bias) { v0 += bias[c]; v1 += bias[c + 1]; }
                size_t idx = orow * ldc + c;
                if (Cf) { Cf[idx] = v0; Cf[idx + 1] = v1; }
                if (Ch) {
                    uint16_t h0, l0, h1, l1;
                    bsplit1(v0, h0, l0); bsplit1(v1, h1, l1);
                    Ch[idx] = h0; Ch[idx + 1] = h1;
                    Cl[idx] = l0; Cl[idx + 1] = l1;
                }
            }
        }
}

// ---------------- scores = q @ k^T per (b,h) ---------------------------------
__global__ void __launch_bounds__(256, 2) scores_lm() {
    MM_PROLOG();
    const int z = blockIdx.z, b = z >> 1, hh = z & 1;
    int row0 = blockIdx.y * 128, col0 = blockIdx.x * 128;
    size_t base = (size_t)(b * NTOK) * EMB + (size_t)hh * HD;
    mm_loop(g_q_h + base, g_q_l + base, EMB, NTOK - 1, row0,
            g_k_h + base, g_k_l + base, EMB, NTOK - 1, col0,
            HD / 32, smu, wm, wn, lane, acc);
    float* C = g_s + (size_t)z * NTOK * SRS;
    int g = lane >> 2, t = lane & 3;
#pragma unroll
    for (int mi = 0; mi < 2; mi++)
#pragma unroll
        for (int e = 0; e < 2; e++) {
            int r = row0 + wm * 32 + mi * 16 + g + e * 8;
            if (r >= NTOK) continue;
#pragma unroll
            for (int ni = 0; ni < 8; ni++) {
                int c = col0 + wn * 64 + ni * 8 + t * 2;
                if (c < NTOK)     C[(size_t)r * SRS + c]     = acc[mi][ni][e * 2 + 0];
                if (c + 1 < NTOK) C[(size_t)r * SRS + c + 1] = acc[mi][ni][e * 2 + 1];
            }
        }
}

// ---------------- o = attn @ v per (b,h) --------------------------------------
__global__ void __launch_bounds__(256, 2) av_lm() {
    MM_PROLOG();
    const int z = blockIdx.z, b = z >> 1, hh = z & 1;
    int row0 = blockIdx.y * 128, col0 = blockIdx.x * 128;
    size_t abase = (size_t)z * NTOK * SRS;
    size_t bbase = ((size_t)b * EMB + (size_t)hh * HD) * SRS;
    mm_loop(g_sx_h + abase, g_sx_l + abase, SRS, NTOK - 1, row0,
            g_vt_h + bbase, g_vt_l + bbase, SRS, HD - 1, col0,
            SRS / 32, smu, wm, wn, lane, acc);
    int g = lane >> 2, t = lane & 3;
#pragma unroll
    for (int mi = 0; mi < 2; mi++)
#pragma unroll
        for (int e = 0; e < 2; e++) {
            int r = row0 + wm * 32 + mi * 16 + g + e * 8;
            if (r >= NTOK) continue;
#pragma unroll
            for (int ni = 0; ni < 8; ni++) {
                int c = col0 + wn * 64 + ni * 8 + t * 2;
                size_t idx = ((size_t)(b * NTOK) + r) * EMB + hh * HD + c;
                uint16_t h0, l0, h1, l1;
                bsplit1(acc[mi][ni][e * 2 + 0], h0, l0);
                bsplit1(acc[mi][ni][e * 2 + 1], h1, l1);
                g_o_h[idx] = h0; g_o_h[idx + 1] = h1;
                g_o_l[idx] = l0; g_o_l[idx + 1] = l1;
            }
        }
}

// ---------------- softmax row / sqrt(768) -> split bf16, zero pads -------------
__global__ void softmax_kernel() {
    size_t row = blockIdx.x;
    const float* r = g_s + row * SRS;
    uint16_t* oh = g_sx_h + row * SRS;
    uint16_t* ol = g_sx_l + row * SRS;
    int tid = threadIdx.x;
    __shared__ float sh[8];
    __shared__ float shb;

    float mx = -1e30f;
    for (int i = tid; i < NTOK; i += 256) mx = fmaxf(mx, r[i]);
    mx = warpMax(mx);
    if ((tid & 31) == 0) sh[tid >> 5] = mx;
    __syncthreads();
    if (tid == 0) {
        float m = sh[0];
#pragma unroll
        for (int i = 1; i < 8; i++) m = fmaxf(m, sh[i]);
        shb = m;
    }
    __syncthreads();
    mx = shb;

    float sum = 0.f;
    float ev[3];
    int cnt = 0;
    for (int i = tid; i < NTOK; i += 256) { ev[cnt] = __expf(r[i] - mx); sum += ev[cnt]; cnt++; }
    sum = warpSum(sum);
    if ((tid & 31) == 0) sh[tid >> 5] = sum;
    __syncthreads();
    if (tid == 0) {
        float s = 0.f;
#pragma unroll
        for (int i = 0; i < 8; i++) s += sh[i];
        shb = s;
    }
    __syncthreads();
    float inv = INV_SQRT_E / shb;
    cnt = 0;
    for (int i = tid; i < NTOK; i += 256) {
        uint16_t h, l;
        bsplit1(ev[cnt++] * inv, h, l);
        oh[i] = h; ol[i] = l;
    }
    if (tid < SRS - NTOK) { oh[NTOK + tid] = 0; ol[NTOK + tid] = 0; }
}

// ---------------- weight transpose + split ------------------------------------
__global__ void wsplit_kernel(const float* __restrict__ W,
                              uint16_t* __restrict__ oh, uint16_t* __restrict__ ol) {
    __shared__ float tile[32][33];
    int tx = threadIdx.x, ty = threadIdx.y;
    int k0 = blockIdx.x * 32, n0 = blockIdx.y * 32;
#pragma unroll
    for (int i = 0; i < 32; i += 8)
        tile[ty + i][tx] = W[(size_t)(k0 + ty + i) * 768 + n0 + tx];
    __syncthreads();
#pragma unroll
    for (int i = 0; i < 32; i += 8) {
        uint16_t h, l;
        bsplit1(tile[tx][ty + i], h, l);
        size_t idx = (size_t)(n0 + ty + i) * 768 + k0 + tx;
        oh[idx] = h; ol[idx] = l;
    }
}

// ---------------- v transpose + split to [b][emb][SRS] --------------------------
__global__ void vtrans_kernel() {
    __shared__ float tile[32][33];
    int tx = threadIdx.x, ty = threadIdx.y;
    int b = blockIdx.z;
    int t0 = blockIdx.x * 32, e0 = blockIdx.y * 32;
    const float* v = g_v + (size_t)b * NTOK * EMB;
#pragma unroll
    for (int i = 0; i < 32; i += 8) {
        int tok = t0 + ty + i;
        tile[ty + i][tx] = (tok < NTOK) ? v[(size_t)tok * EMB + e0 + tx] : 0.f;
    }
    __syncthreads();
#pragma unroll
    for (int i = 0; i < 32; i += 8) {
        int tok = t0 + tx, e = e0 + ty + i;
        if (tok < SRS) {
            uint16_t h, l;
            bsplit1(tile[tx][ty + i], h, l);
            size_t idx = ((size_t)b * EMB + e) * SRS + tok;
            g_vt_h[idx] = h; g_vt_l[idx] = l;
        }
    }
}

// ---------------- elementwise fp32 -> split -------------------------------------
__global__ void split_pa_kernel(const float* __restrict__ in, long n) {
    long i = (long)blockIdx.x * blockDim.x + threadIdx.x;
    if (i >= n) return;
    uint16_t h, l;
    bsplit1(in[i], h, l);
    g_pa_h[i] = h; g_pa_l[i] = l;
}

// ---------------- patch gather --------------------------------------------------
__global__ void patch_extract(const float* __restrict__ x) {
    long idx = (long)blockIdx.x * blockDim.x + threadIdx.x;
    const long total = (long)BATCH * 3 * 384 * 384;
    if (idx >= total) return;
    int ww = (int)(idx % 384);
    long t1 = idx / 384;
    int hh = (int)(t1 % 384);
    long t2 = t1 / 384;
    int c = (int)(t2 % 3);
    int b = (int)(t2 / 3);
    int j = (hh >> 4) * 24 + (ww >> 4);
    int k = (hh & 15) * 48 + (ww & 15) * 3 + c;
    g_f[((size_t)(b * NP + j)) * EMB + k] = x[idx];
}

__global__ void fill_cls_text(const float* __restrict__ cls, const float* __restrict__ txt) {
    long idx = (long)blockIdx.x * blockDim.x + threadIdx.x;
    const long total = (long)BATCH * (1 + NTXT) * EMB;
    if (idx >= total) return;
    int e = (int)(idx % EMB);
    long r = idx / EMB;
    int tok = (int)(r % (1 + NTXT));
    int b = (int)(r / (1 + NTXT));
    if (tok == 0)
        g_t[((size_t)b * NTOK) * EMB + e] = cls[e];
    else
        g_t[((size_t)b * NTOK + NP + tok) * EMB + e] = txt[((size_t)b * NTXT + (tok - 1)) * EMB + e];
}

// ---------------- LayerNorm 768 --------------------------------------------------
__device__ __forceinline__ void ln_stats(const float* r, int tid, float v[3],
                                         float& mean, float& rstd) {
    v[0] = r[tid]; v[1] = r[tid + 256]; v[2] = r[tid + 512];
    float s = v[0] + v[1] + v[2];
    float ss = v[0] * v[0] + v[1] * v[1] + v[2] * v[2];
    s = warpSum(s); ss = warpSum(ss);
    __shared__ float sh1[8], sh2[8];
    __shared__ float smean, srstd;
    if ((tid & 31) == 0) { sh1[tid >> 5] = s; sh2[tid >> 5] = ss; }
    __syncthreads();
    if (tid == 0) {
        float a = 0.f, b2 = 0.f;
#pragma unroll
        for (int i = 0; i < 8; i++) { a += sh1[i]; b2 += sh2[i]; }
        float m = a * (1.f / 768.f);
        smean = m;
        srstd = rsqrtf(b2 * (1.f / 768.f) - m * m + 1e-5f);
    }
    __syncthreads();
    mean = smean; rstd = srstd;
}

__global__ void ln768_split(const float* __restrict__ in,
                            const float* __restrict__ g, const float* __restrict__ be,
                            uint16_t* __restrict__ oh, uint16_t* __restrict__ ol) {
    size_t row = blockIdx.x;
    int tid = threadIdx.x;
    float v[3], mean, rstd;
    ln_stats(in + row * EMB, tid, v, mean, rstd);
#pragma unroll
    for (int i = 0; i < 3; i++) {
        int c = tid + i * 256;
        float val = (v[i] - mean) * rstd * g[c] + be[c];
        uint16_t h, l;
        bsplit1(val, h, l);
        oh[row * EMB + c] = h; ol[row * EMB + c] = l;
    }
}

__global__ void ln768_add(const float* __restrict__ in,
                          const float* __restrict__ g, const float* __restrict__ be,
                          float* __restrict__ out) {
    size_t row = blockIdx.x;
    int tid = threadIdx.x;
    float v[3], mean, rstd;
    ln_stats(in + row * EMB, tid, v, mean, rstd);
#pragma unroll
    for (int i = 0; i < 3; i++) {
        int c = tid + i * 256;
        out[row * EMB + c] += (v[i] - mean) * rstd * g[c] + be[c];
    }
}

__global__ void meanpool_kernel() {
    int b = blockIdx.x;
    int e = threadIdx.x;
    const float* base = g_t + (size_t)b * NTOK * EMB + e;
    float s = 0.f;
    for (int i = 0; i < NTOK; i++) s += base[(size_t)i * EMB];
    g_m[b * EMB + e] = s * (1.f / (float)NTOK);
}

// ---------------- launch -----------------------------------------------------------
extern "C" void kernel_launch(void* const* d_in, const int* in_sizes, int n_in,
                              void* d_out, int out_size) {
    const float* x    = (const float*)d_in[0];
    const float* txt  = (const float*)d_in[1];
    const float* Wpa  = (const float*)d_in[2];
    const float* bpa  = (const float*)d_in[3];
    const float* cls  = (const float*)d_in[4];
    const float* g1   = (const float*)d_in[5];
    const float* be1  = (const float*)d_in[6];
    const float* Wq   = (const float*)d_in[7];
    const float* bq   = (const float*)d_in[8];
    const float* Wk   = (const float*)d_in[9];
    const float* bk   = (const float*)d_in[10];
    const float* Wv   = (const float*)d_in[11];
    const float* bv   = (const float*)d_in[12];
    const float* Wp   = (const float*)d_in[13];
    const float* bp   = (const float*)d_in[14];
    const float* g2   = (const float*)d_in[15];
    const float* be2  = (const float*)d_in[16];
    const float* g3   = (const float*)d_in[17];
    const float* be3  = (const float*)d_in[18];
    const float* Wf   = (const float*)d_in[19];
    const float* bf   = (const float*)d_in[20];
    float* out = (float*)d_out;

    cudaFuncSetAttribute(gemm_lm, cudaFuncAttributeMaxDynamicSharedMemorySize, DSMB);
    cudaFuncSetAttribute(scores_lm, cudaFuncAttributeMaxDynamicSharedMemorySize, DSMB);
    cudaFuncSetAttribute(av_lm, cudaFuncAttributeMaxDynamicSharedMemorySize, DSMB);

    float *t, *f, *m;
    uint16_t *wh, *wl, *pah, *pal, *hh, *hl, *qh, *ql, *kh, *kl, *oh, *ol, *mh, *ml;
    float* v32;
    cudaGetSymbolAddress((void**)&t, g_t);
    cudaGetSymbolAddress((void**)&f, g_f);
    cudaGetSymbolAddress((void**)&m, g_m);
    cudaGetSymbolAddress((void**)&v32, g_v);
    cudaGetSymbolAddress((void**)&wh, g_wh);
    cudaGetSymbolAddress((void**)&wl, g_wl);
    cudaGetSymbolAddress((void**)&pah, g_pa_h);
    cudaGetSymbolAddress((void**)&pal, g_pa_l);
    cudaGetSymbolAddress((void**)&hh, g_h_h);
    cudaGetSymbolAddress((void**)&hl, g_h_l);
    cudaGetSymbolAddress((void**)&qh, g_q_h);
    cudaGetSymbolAddress((void**)&ql, g_q_l);
    cudaGetSymbolAddress((void**)&kh, g_k_h);
    cudaGetSymbolAddress((void**)&kl, g_k_l);
    cudaGetSymbolAddress((void**)&oh, g_o_h);
    cudaGetSymbolAddress((void**)&ol, g_o_l);
    cudaGetSymbolAddress((void**)&mh, g_m_h);
    cudaGetSymbolAddress((void**)&ml, g_m_l);

    const int MQKV = BATCH * NTOK;    // 20928
    const int MPATCH = BATCH * NP;    // 18432
    const size_t WSZ = 768 * 768;
    dim3 tb(32, 8), wgrid(24, 24);

    // weight transpose+split (0=Wpa 1=Wq 2=Wk 3=Wv 4=Wp 5=Wf)
    wsplit_kernel<<<wgrid, tb>>>(Wpa, wh + 0 * WSZ, wl + 0 * WSZ);
    wsplit_kernel<<<wgrid, tb>>>(Wq,  wh + 1 * WSZ, wl + 1 * WSZ);
    wsplit_kernel<<<wgrid, tb>>>(Wk,  wh + 2 * WSZ, wl + 2 * WSZ);
    wsplit_kernel<<<wgrid, tb>>>(Wv,  wh + 3 * WSZ, wl + 3 * WSZ);
    wsplit_kernel<<<wgrid, tb>>>(Wp,  wh + 4 * WSZ, wl + 4 * WSZ);
    wsplit_kernel<<<wgrid, tb>>>(Wf,  wh + 5 * WSZ, wl + 5 * WSZ);

    // patches
    patch_extract<<<55296, 256>>>(x);
    split_pa_kernel<<<(int)((PAW + 255) / 256), 256>>>(f, (long)PAW);
    fill_cls_text<<<7488, 256>>>(cls, txt);

    // patch GEMM -> t fp32 (remapped rows)
    gemm_lm<<<dim3(6, 144), 256, DSMB>>>(pah, pal, EMB, wh + 0 * WSZ, wl + 0 * WSZ,
                                         bpa, t, nullptr, nullptr, EMB, MPATCH, 24, 1);

    // LN1 -> h split
    ln768_split<<<MQKV, 256>>>(t, g1, be1, hh, hl);

    // QKV
    dim3 gq(6, (MQKV + 127) / 128);
    gemm_lm<<<gq, 256, DSMB>>>(hh, hl, EMB, wh + 1 * WSZ, wl + 1 * WSZ, bq,
                               nullptr, qh, ql, EMB, MQKV, 24, 0);
    gemm_lm<<<gq, 256, DSMB>>>(hh, hl, EMB, wh + 2 * WSZ, wl + 2 * WSZ, bk,
                               nullptr, kh, kl, EMB, MQKV, 24, 0);
    gemm_lm<<<gq, 256, DSMB>>>(hh, hl, EMB, wh + 3 * WSZ, wl + 3 * WSZ, bv,
                               v32, nullptr, nullptr, EMB, MQKV, 24, 0);

    // v transpose+split (pad k to SRS)
    vtrans_kernel<<<dim3(SRS / 32, 24, BATCH), tb>>>();

    // attention
    scores_lm<<<dim3(6, 6, 64), 256, DSMB>>>();
    softmax_kernel<<<64 * NTOK, 256>>>();
    av_lm<<<dim3(3, 6, 64), 256, DSMB>>>();

    // proj -> f fp32, then t += LN2(f)
    gemm_lm<<<gq, 256, DSMB>>>(oh, ol, EMB, wh + 4 * WSZ, wl + 4 * WSZ, bp,
                               f, nullptr, nullptr, EMB, MQKV, 24, 0);
    ln768_add<<<MQKV, 256>>>(f, g2, be2, t);

    // pool, LN3 -> split, final GEMM -> out
    meanpool_kernel<<<BATCH, 768>>>();
    ln768_split<<<BATCH, 256>>>(m, g3, be3, mh, ml);
    gemm_lm<<<dim3(6, 1), 256, DSMB>>>(mh, ml, EMB, wh + 5 * WSZ, wl + 5 * WSZ, bf,
                                       out, nullptr, nullptr, EMB, 32, 24, 0);
}